// round 14
// baseline (speedup 1.0000x reference)
#include <cuda_runtime.h>
#include <cuda_fp16.h>
#include <cstdint>
#include <math.h>

#define BB 4
#define CC 256
#define CI 32
#define NN 4096
#define ROWS 320

__device__ __align__(256) __half g_x16[(size_t)BB * CC * NN];
__device__ __align__(256) __half g_QKV16[(size_t)BB * ROWS * NN];

// ===========================================================================
// Portable PTX helpers
// ===========================================================================
__device__ __forceinline__ uint32_t smem_to_u32(const void* p) {
    uint32_t a;
    asm("{ .reg .u64 t; cvta.to.shared.u64 t, %1; cvt.u32.u64 %0, t; }" : "=r"(a) : "l"(p));
    return a;
}
__device__ __forceinline__ void cp16(uint32_t dst, const void* src) {
    asm volatile("cp.async.ca.shared.global [%0], [%1], 16;" :: "r"(dst), "l"(src) : "memory");
}
#define CP_COMMIT() asm volatile("cp.async.commit_group;" ::: "memory")
#define CP_WAIT(n)  asm volatile("cp.async.wait_group %0;" :: "n"(n) : "memory")
#define BAR_SYNC(id, n)   asm volatile("bar.sync %0, %1;"   :: "r"(id), "r"(n) : "memory")
#define BAR_ARRIVE(id, n) asm volatile("bar.arrive %0, %1;" :: "r"(id), "r"(n) : "memory")

__device__ __forceinline__ void ldsm_x4(uint32_t* r, uint32_t addr) {
    asm volatile("ldmatrix.sync.aligned.m8n8.x4.shared.b16 {%0,%1,%2,%3}, [%4];"
        : "=r"(r[0]), "=r"(r[1]), "=r"(r[2]), "=r"(r[3]) : "r"(addr));
}
__device__ __forceinline__ void ldsm_x4t(uint32_t* r, uint32_t addr) {
    asm volatile("ldmatrix.sync.aligned.m8n8.x4.trans.shared.b16 {%0,%1,%2,%3}, [%4];"
        : "=r"(r[0]), "=r"(r[1]), "=r"(r[2]), "=r"(r[3]) : "r"(addr));
}
// fp32-accumulate (S phase)
__device__ __forceinline__ void mma16(float* d, const uint32_t* a, uint32_t b0, uint32_t b1) {
    asm volatile(
        "mma.sync.aligned.m16n8k16.row.col.f32.f16.f16.f32 "
        "{%0,%1,%2,%3}, {%4,%5,%6,%7}, {%8,%9}, {%0,%1,%2,%3};"
        : "+f"(d[0]), "+f"(d[1]), "+f"(d[2]), "+f"(d[3])
        : "r"(a[0]), "r"(a[1]), "r"(a[2]), "r"(a[3]), "r"(b0), "r"(b1));
}
// fp16-accumulate (PV phase, per-tile chains only)
__device__ __forceinline__ void mma16h(uint32_t* d, const uint32_t* a, uint32_t b0, uint32_t b1) {
    asm volatile(
        "mma.sync.aligned.m16n8k16.row.col.f16.f16.f16.f16 "
        "{%0,%1}, {%2,%3,%4,%5}, {%6,%7}, {%0,%1};"
        : "+r"(d[0]), "+r"(d[1])
        : "r"(a[0]), "r"(a[1]), "r"(a[2]), "r"(a[3]), "r"(b0), "r"(b1));
}
__device__ __forceinline__ uint32_t h2u(__half2 h) {
    uint32_t u; memcpy(&u, &h, 4); return u;
}

// ===========================================================================
// Kernel 0: elementwise x fp32 -> fp16
// ===========================================================================
__global__ void convx16_kernel(const float* __restrict__ x) {
    size_t i = (size_t)blockIdx.x * 256 + threadIdx.x;
    float4 v = ((const float4*)x)[i];
    uint2 o;
    o.x = h2u(__floats2half2_rn(v.x, v.y));
    o.y = h2u(__floats2half2_rn(v.z, v.w));
    ((uint2*)g_x16)[i] = o;
}

// ===========================================================================
// Kernel 1: QKV projection (R13, banked)
// ===========================================================================
#define PJ_WS 0
#define PJ_X0 33792
#define PJ_X1 67584
#define PJ_SMEM 101376

__global__ __launch_bounds__(256) void proj_kernel(const float* __restrict__ Wq, const float* __restrict__ bq,
                                                   const float* __restrict__ Wk, const float* __restrict__ bk,
                                                   const float* __restrict__ Wv, const float* __restrict__ bv) {
    extern __shared__ __align__(128) char psm[];
    const uint32_t sb = smem_to_u32(psm);
    const int tid = threadIdx.x;
    const int w = tid >> 5, lane = tid & 31;
    const int lq = lane >> 2, lt4 = lane & 3;
    const int wm = w & 3, wn = w >> 2;
    const int b = blockIdx.z;
    const int rowbase = blockIdx.y * 64;
    const int nbase = blockIdx.x * 256;
    const __half* xg = g_x16 + (size_t)b * CC * NN;

#pragma unroll
    for (int i = 0; i < 8; i++) {
        int idx = tid + i * 256, c = idx >> 5, j = idx & 31;
        cp16(sb + PJ_X0 + c * 528 + j * 16, xg + (size_t)c * NN + nbase + j * 8);
    }
    CP_COMMIT();
#pragma unroll
    for (int i = 0; i < 8; i++) {
        int idx = tid + i * 256, c = idx >> 5, j = idx & 31;
        cp16(sb + PJ_X1 + c * 528 + j * 16, xg + (size_t)(64 + c) * NN + nbase + j * 8);
    }
    CP_COMMIT();

#pragma unroll
    for (int i = 0; i < 16; i++) {
        int idx = tid + i * 256;
        int r = idx >> 6, kq = idx & 63;
        int gm = rowbase + r;
        const float* src;
        if (gm < CI)            src = Wq + (size_t)gm * CC;
        else if (gm < 2 * CI)   src = Wk + (size_t)(gm - CI) * CC;
        else                    src = Wv + (size_t)(gm - 2 * CI) * CC;
        float4 v = *(const float4*)(src + kq * 4);
        *(__half2*)(psm + PJ_WS + r * 528 + kq * 8)     = __floats2half2_rn(v.x, v.y);
        *(__half2*)(psm + PJ_WS + r * 528 + kq * 8 + 4) = __floats2half2_rn(v.z, v.w);
    }

    float acc[16][4];
#pragma unroll
    for (int i = 0; i < 16; i++)
#pragma unroll
        for (int e = 0; e < 4; e++) acc[i][e] = 0.f;

    const uint32_t aoffL = (uint32_t)((wm * 16 + (lane & 15)) * 528 + (lane >> 4) * 16);
    const uint32_t xtr = (uint32_t)((lane >> 4) * 8 + (lane & 7));
    const uint32_t ytr = (uint32_t)(((lane >> 3) & 1) * 16);

    CP_WAIT(1);
    __syncthreads();

#pragma unroll
    for (int kc = 0; kc < 4; kc++) {
        const uint32_t xbuf = sb + ((kc & 1) ? PJ_X1 : PJ_X0);
#pragma unroll
        for (int ks = 0; ks < 4; ks++) {
            uint32_t a[4];
            ldsm_x4(a, sb + PJ_WS + aoffL + (kc * 64 + ks * 16) * 2);
#pragma unroll
            for (int nt2 = 0; nt2 < 8; nt2++) {
                uint32_t bf[4];
                ldsm_x4t(bf, xbuf + (ks * 16 + xtr) * 528 + (wn * 128 + nt2 * 16) * 2 + ytr);
                mma16(acc[2 * nt2], a, bf[0], bf[2]);
                mma16(acc[2 * nt2 + 1], a, bf[1], bf[3]);
            }
        }
        __syncthreads();
        if (kc + 2 < 4) {
            uint32_t xdst = sb + ((kc & 1) ? PJ_X1 : PJ_X0);
#pragma unroll
            for (int i = 0; i < 8; i++) {
                int idx = tid + i * 256, c = idx >> 5, j = idx & 31;
                cp16(xdst + c * 528 + j * 16, xg + (size_t)((kc + 2) * 64 + c) * NN + nbase + j * 8);
            }
            CP_COMMIT();
            CP_WAIT(1);
        } else {
            CP_WAIT(0);
        }
        __syncthreads();
    }

    const int m0 = rowbase + wm * 16 + lq, m1 = m0 + 8;
    float bias0, bias1;
    bias0 = (m0 < CI) ? bq[m0] : (m0 < 2 * CI) ? bk[m0 - CI] : bv[m0 - 2 * CI];
    bias1 = (m1 < CI) ? bq[m1] : (m1 < 2 * CI) ? bk[m1 - CI] : bv[m1 - 2 * CI];
    __half* og = g_QKV16 + (size_t)b * ROWS * NN;
#pragma unroll
    for (int nt = 0; nt < 16; nt++) {
        int n = nbase + wn * 128 + nt * 8 + 2 * lt4;
        *(__half2*)(og + (size_t)m0 * NN + n) = __floats2half2_rn(acc[nt][0] + bias0, acc[nt][1] + bias0);
        *(__half2*)(og + (size_t)m1 * NN + n) = __floats2half2_rn(acc[nt][2] + bias1, acc[nt][3] + bias1);
    }
}

// ===========================================================================
// Kernel 2: flash attention, BQ=64, 320 threads, 2 CTAs/SM (R7 structure),
// PV via fp16-accumulate mma + per-tile fp32 fold.
// warps 0-1 = S-warps (32 q-rows each); warps 2-9 = V-warps (32 channels each).
// ===========================================================================
#define BQ 64
#define BK 64
#define NT (NN / BK)
#define KVT 144

#define SM_Q    0                      // 32 x 144 = 4608
#define KBUF(i) (4608 + (i) * 4608)
#define VBUF(i) (13824 + (i) * 36864)
#define PBUF(i) (87552 + (i) * 9216)
#define SM_MREF 105984
#define SM_ALPH 106240                 // float[2][64]
#define SM_LROW 106752
#define SM_FLAG 107008                 // int[4]
#define SMEM_AT 107040

#define BID_PRDY 1
#define BID_PFRE 3
#define BID_SBAR 5
#define BID_VBAR 6

__global__ __launch_bounds__(320, 2) void attn_kernel(const float* __restrict__ x,
                                                      const float* __restrict__ gamma_p,
                                                      float* __restrict__ out) {
    extern __shared__ __align__(128) char smem[];
    const uint32_t sb = smem_to_u32(smem);
    float* mref = (float*)(smem + SM_MREF);
    float* alph = (float*)(smem + SM_ALPH);
    float* lrow = (float*)(smem + SM_LROW);
    int* flagv  = (int*)(smem + SM_FLAG);

    const int tid = threadIdx.x;
    const int w = tid >> 5, lane = tid & 31;
    const int lq = lane >> 2, lt4 = lane & 3;
    const int b = blockIdx.y;
    const int qbase = blockIdx.x * BQ;

    const __half* Qg = g_QKV16 + (size_t)b * ROWS * NN;
    const __half* Kg = Qg + (size_t)CI * NN;
    const __half* Vg = Qg + (size_t)2 * CI * NN;

    for (int idx = tid; idx < 256; idx += 320) {
        int c = idx >> 3, j = idx & 7;
        cp16(sb + SM_Q + c * KVT + j * 16, Qg + (size_t)c * NN + qbase + j * 8);
    }
    if (tid < 64) {
#pragma unroll
        for (int i = 0; i < 4; i++) {
            int idx = tid + i * 64, c = idx >> 3, j = idx & 7;
            cp16(sb + KBUF(0) + c * KVT + j * 16, Kg + (size_t)c * NN + j * 8);
        }
    } else {
        int vt = tid - 64;
#pragma unroll
        for (int i = 0; i < 8; i++) {
            int idx = vt + i * 256, ch = idx >> 3, j = idx & 7;
            cp16(sb + VBUF(0) + ch * KVT + j * 16, Vg + (size_t)ch * NN + j * 8);
        }
    }
    CP_COMMIT();
    if (tid < BQ) mref[tid] = -1e30f;
    CP_WAIT(0);
    __syncthreads();

    const uint32_t xtr = (uint32_t)((lane >> 4) * 8 + (lane & 7));
    const uint32_t ytr = (uint32_t)(((lane >> 3) & 1) * 16);
    const uint32_t ant = (uint32_t)((lane & 15) * KVT + (lane >> 4) * 16);
    const uint32_t bnt = (uint32_t)((((lane >> 3) & 1) * 8 + (lane & 7)) * KVT + (lane >> 4) * 16);

    if (w < 2) {
        // =================== S-warps ===================
        const int sw = w;
        uint32_t aq[2][2][4];
#pragma unroll
        for (int rg = 0; rg < 2; rg++)
#pragma unroll
            for (int ks = 0; ks < 2; ks++)
                ldsm_x4t(aq[rg][ks], sb + SM_Q + (ks * 16 + xtr) * KVT + (sw * 32 + rg * 16) * 2 + ytr);

        float l00 = 0.f, l01 = 0.f, l10 = 0.f, l11 = 0.f;

#pragma unroll 1
        for (int t = 0; t < NT; t++) {
            const int bi = t & 1;
            BAR_SYNC(BID_SBAR, 64);
            if (t + 1 < NT) {
                uint32_t kd = sb + KBUF((t + 1) & 1);
                const int kt1 = (t + 1) * BK;
#pragma unroll
                for (int i = 0; i < 4; i++) {
                    int idx = tid + i * 64, c = idx >> 3, j = idx & 7;
                    cp16(kd + c * KVT + j * 16, Kg + (size_t)c * NN + kt1 + j * 8);
                }
                CP_COMMIT();
                CP_WAIT(1);
            } else {
                CP_WAIT(0);
            }
            BAR_SYNC(BID_SBAR, 64);

            const uint32_t kbuf = sb + KBUF(bi);
            float sacc[2][8][4];
#pragma unroll
            for (int rg = 0; rg < 2; rg++)
#pragma unroll
                for (int nt = 0; nt < 8; nt++)
#pragma unroll
                    for (int e = 0; e < 4; e++) sacc[rg][nt][e] = 0.f;
#pragma unroll
            for (int ks = 0; ks < 2; ks++) {
#pragma unroll
                for (int nt2 = 0; nt2 < 4; nt2++) {
                    uint32_t kb[4];
                    ldsm_x4t(kb, kbuf + (ks * 16 + xtr) * KVT + nt2 * 32 + ytr);
#pragma unroll
                    for (int rg = 0; rg < 2; rg++) {
                        mma16(sacc[rg][2 * nt2], aq[rg][ks], kb[0], kb[2]);
                        mma16(sacc[rg][2 * nt2 + 1], aq[rg][ks], kb[1], kb[3]);
                    }
                }
            }

            BAR_SYNC(BID_PFRE + bi, 320);

            bool anyflag = false;
#pragma unroll
            for (int rg = 0; rg < 2; rg++) {
                const int row0 = sw * 32 + rg * 16 + lq, row1 = row0 + 8;
                float tm0 = -1e30f, tm1 = -1e30f;
#pragma unroll
                for (int nt = 0; nt < 8; nt++) {
                    tm0 = fmaxf(tm0, fmaxf(sacc[rg][nt][0], sacc[rg][nt][1]));
                    tm1 = fmaxf(tm1, fmaxf(sacc[rg][nt][2], sacc[rg][nt][3]));
                }
                tm0 = fmaxf(tm0, __shfl_xor_sync(0xffffffffu, tm0, 1));
                tm0 = fmaxf(tm0, __shfl_xor_sync(0xffffffffu, tm0, 2));
                tm1 = fmaxf(tm1, __shfl_xor_sync(0xffffffffu, tm1, 1));
                tm1 = fmaxf(tm1, __shfl_xor_sync(0xffffffffu, tm1, 2));
                const float mold0 = mref[row0], mold1 = mref[row1];
                const float mnew0 = (tm0 > mold0 + 6.f) ? tm0 : mold0;
                const float mnew1 = (tm1 > mold1 + 6.f) ? tm1 : mold1;
                const float alpha0 = __expf(mold0 - mnew0);
                const float alpha1 = __expf(mold1 - mnew1);
                if (lt4 == 0) {
                    mref[row0] = mnew0; alph[bi * 64 + row0] = alpha0;
                    mref[row1] = mnew1; alph[bi * 64 + row1] = alpha1;
                }
                anyflag |= (mnew0 != mold0) | (mnew1 != mold1);
                float ts0 = 0.f, ts1 = 0.f;
#pragma unroll
                for (int nt = 0; nt < 8; nt++) {
                    float p0 = __expf(sacc[rg][nt][0] - mnew0);
                    float p1 = __expf(sacc[rg][nt][1] - mnew0);
                    float p2 = __expf(sacc[rg][nt][2] - mnew1);
                    float p3 = __expf(sacc[rg][nt][3] - mnew1);
                    ts0 += p0 + p1; ts1 += p2 + p3;
                    int mb = (nt * 8 + 2 * lt4) * 2;
                    *(__half2*)(smem + PBUF(bi) + row0 * KVT + mb) = __floats2half2_rn(p0, p1);
                    *(__half2*)(smem + PBUF(bi) + row1 * KVT + mb) = __floats2half2_rn(p2, p3);
                }
                if (rg == 0) { l00 = l00 * alpha0 + ts0; l01 = l01 * alpha1 + ts1; }
                else         { l10 = l10 * alpha0 + ts0; l11 = l11 * alpha1 + ts1; }
            }
            int any = __any_sync(0xffffffffu, anyflag);
            if (lane == 0) flagv[bi * 2 + sw] = any;
            BAR_ARRIVE(BID_PRDY + bi, 320);
        }

        l00 += __shfl_xor_sync(0xffffffffu, l00, 1); l00 += __shfl_xor_sync(0xffffffffu, l00, 2);
        l01 += __shfl_xor_sync(0xffffffffu, l01, 1); l01 += __shfl_xor_sync(0xffffffffu, l01, 2);
        l10 += __shfl_xor_sync(0xffffffffu, l10, 1); l10 += __shfl_xor_sync(0xffffffffu, l10, 2);
        l11 += __shfl_xor_sync(0xffffffffu, l11, 1); l11 += __shfl_xor_sync(0xffffffffu, l11, 2);
        if (lt4 == 0) {
            lrow[sw * 32 + lq] = l00;       lrow[sw * 32 + lq + 8] = l01;
            lrow[sw * 32 + 16 + lq] = l10;  lrow[sw * 32 + 16 + lq + 8] = l11;
        }
        __syncthreads();
    } else {
        // =================== V-warps (fp16-accum PV) ===================
        const int vw = w - 2;
        BAR_ARRIVE(BID_PFRE + 0, 320);
        BAR_ARRIVE(BID_PFRE + 1, 320);

        float Oacc[64];
#pragma unroll
        for (int i = 0; i < 64; i++) Oacc[i] = 0.f;

#pragma unroll 1
        for (int t = 0; t < NT; t++) {
            const int bi = t & 1;
            BAR_SYNC(BID_VBAR, 256);
            if (t + 1 < NT) {
                uint32_t vd = sb + VBUF((t + 1) & 1);
                const int kt1 = (t + 1) * BK;
                int vt = tid - 64;
#pragma unroll
                for (int i = 0; i < 8; i++) {
                    int idx = vt + i * 256, ch = idx >> 3, j = idx & 7;
                    cp16(vd + ch * KVT + j * 16, Vg + (size_t)ch * NN + kt1 + j * 8);
                }
                CP_COMMIT();
                CP_WAIT(1);
            } else {
                CP_WAIT(0);
            }
            BAR_SYNC(BID_VBAR, 256);
            BAR_SYNC(BID_PRDY + bi, 320);

            // rescale fp32 master by alpha (before folding this tile)
            int flag = flagv[bi * 2] | flagv[bi * 2 + 1];
            if (flag) {
#pragma unroll
                for (int mt = 0; mt < 4; mt++) {
                    float a0 = alph[bi * 64 + mt * 16 + lq];
                    float a1 = alph[bi * 64 + mt * 16 + lq + 8];
#pragma unroll
                    for (int nt = 0; nt < 4; nt++) {
                        float* o = &Oacc[(mt * 4 + nt) * 4];
                        o[0] *= a0; o[1] *= a0; o[2] *= a1; o[3] *= a1;
                    }
                }
            }

            // fp16 fragment accumulation over this tile's 64 keys
            uint32_t frag[16][2];
#pragma unroll
            for (int u = 0; u < 16; u++) { frag[u][0] = 0u; frag[u][1] = 0u; }

            const uint32_t vbuf = sb + VBUF(bi);
            const uint32_t pbuf = sb + PBUF(bi);
#pragma unroll
            for (int ks = 0; ks < 4; ks++) {
                uint32_t vb0[4], vb1[4];
                {
                    uint32_t tr[4];
                    ldsm_x4(tr, vbuf + bnt + (vw * 32) * KVT + ks * 32);
                    vb0[0] = tr[0]; vb0[1] = tr[1]; vb1[0] = tr[2]; vb1[1] = tr[3];
                    ldsm_x4(tr, vbuf + bnt + (vw * 32 + 16) * KVT + ks * 32);
                    vb0[2] = tr[0]; vb0[3] = tr[1]; vb1[2] = tr[2]; vb1[3] = tr[3];
                }
#pragma unroll
                for (int mt = 0; mt < 4; mt++) {
                    uint32_t a[4];
                    ldsm_x4(a, pbuf + ant + (mt * 16) * KVT + ks * 32);
#pragma unroll
                    for (int nt = 0; nt < 4; nt++)
                        mma16h(frag[mt * 4 + nt], a, vb0[nt], vb1[nt]);
                }
            }
            BAR_ARRIVE(BID_PFRE + bi, 320);

            // fold fp16 tile partial into fp32 master
#pragma unroll
            for (int u = 0; u < 16; u++) {
                float2 lo = __half22float2(*(__half2*)&frag[u][0]);
                float2 hi = __half22float2(*(__half2*)&frag[u][1]);
                float* o = &Oacc[u * 4];
                o[0] += lo.x; o[1] += lo.y; o[2] += hi.x; o[3] += hi.y;
            }
        }

        __syncthreads();

        const float g = gamma_p[0];
        const float* xb = x + (size_t)b * CC * NN;
        float* ob = out + (size_t)b * CC * NN;
#pragma unroll
        for (int mt = 0; mt < 4; mt++) {
            float s0 = g / lrow[mt * 16 + lq];
            float s1 = g / lrow[mt * 16 + lq + 8];
            int na = qbase + mt * 16 + lq;
#pragma unroll
            for (int nt = 0; nt < 4; nt++) {
                int ch = vw * 32 + nt * 8 + 2 * lt4;
                const float* o = &Oacc[(mt * 4 + nt) * 4];
                size_t i00 = (size_t)ch * NN + na;
                size_t i10 = (size_t)(ch + 1) * NN + na;
                ob[i00] = o[0] * s0 + xb[i00];
                ob[i10] = o[1] * s0 + xb[i10];
                ob[i00 + 8] = o[2] * s1 + xb[i00 + 8];
                ob[i10 + 8] = o[3] * s1 + xb[i10 + 8];
            }
        }
    }
}

// ===========================================================================
// Launch
// ===========================================================================
extern "C" void kernel_launch(void* const* d_in, const int* in_sizes, int n_in,
                              void* d_out, int out_size) {
    const float* x  = (const float*)d_in[0];
    const float* Wq = (const float*)d_in[1];
    const float* bq = (const float*)d_in[2];
    const float* Wk = (const float*)d_in[3];
    const float* bk = (const float*)d_in[4];
    const float* Wv = (const float*)d_in[5];
    const float* bv = (const float*)d_in[6];
    const float* gamma = (const float*)d_in[7];
    float* out = (float*)d_out;

    static int cfg = 0;
    if (!cfg) {
        cudaFuncSetAttribute(proj_kernel, cudaFuncAttributeMaxDynamicSharedMemorySize, PJ_SMEM);
        cudaFuncSetAttribute(attn_kernel, cudaFuncAttributeMaxDynamicSharedMemorySize, SMEM_AT);
        cfg = 1;
    }

    convx16_kernel<<<(BB * CC * NN / 4) / 256, 256>>>(x);

    dim3 pgrid(NN / 256, ROWS / 64, BB);
    proj_kernel<<<pgrid, 256, PJ_SMEM>>>(Wq, bq, Wk, bk, Wv, bv);

    dim3 agrid(NN / BQ, BB);
    attn_kernel<<<agrid, 320, SMEM_AT>>>(x, gamma, out);
}

// round 15
// speedup vs baseline: 1.3853x; 1.3853x over previous
#include <cuda_runtime.h>
#include <cuda_fp16.h>
#include <cstdint>
#include <math.h>

#define BB 4
#define CC 256
#define CI 32
#define NN 4096
#define ROWS 320

__device__ __align__(256) __half g_x16[(size_t)BB * CC * NN];
__device__ __align__(256) __half g_QKV16[(size_t)BB * ROWS * NN];

// ===========================================================================
// Portable PTX helpers
// ===========================================================================
__device__ __forceinline__ uint32_t smem_to_u32(const void* p) {
    uint32_t a;
    asm("{ .reg .u64 t; cvta.to.shared.u64 t, %1; cvt.u32.u64 %0, t; }" : "=r"(a) : "l"(p));
    return a;
}
__device__ __forceinline__ void cp16(uint32_t dst, const void* src) {
    asm volatile("cp.async.ca.shared.global [%0], [%1], 16;" :: "r"(dst), "l"(src) : "memory");
}
#define CP_COMMIT() asm volatile("cp.async.commit_group;" ::: "memory")
#define CP_WAIT(n)  asm volatile("cp.async.wait_group %0;" :: "n"(n) : "memory")
#define BAR_SYNC(id, n)   asm volatile("bar.sync %0, %1;"   :: "r"(id), "r"(n) : "memory")
#define BAR_ARRIVE(id, n) asm volatile("bar.arrive %0, %1;" :: "r"(id), "r"(n) : "memory")

__device__ __forceinline__ void ldsm_x4(uint32_t* r, uint32_t addr) {
    asm volatile("ldmatrix.sync.aligned.m8n8.x4.shared.b16 {%0,%1,%2,%3}, [%4];"
        : "=r"(r[0]), "=r"(r[1]), "=r"(r[2]), "=r"(r[3]) : "r"(addr));
}
__device__ __forceinline__ void ldsm_x4t(uint32_t* r, uint32_t addr) {
    asm volatile("ldmatrix.sync.aligned.m8n8.x4.trans.shared.b16 {%0,%1,%2,%3}, [%4];"
        : "=r"(r[0]), "=r"(r[1]), "=r"(r[2]), "=r"(r[3]) : "r"(addr));
}
__device__ __forceinline__ void mma16(float* d, const uint32_t* a, uint32_t b0, uint32_t b1) {
    asm volatile(
        "mma.sync.aligned.m16n8k16.row.col.f32.f16.f16.f32 "
        "{%0,%1,%2,%3}, {%4,%5,%6,%7}, {%8,%9}, {%0,%1,%2,%3};"
        : "+f"(d[0]), "+f"(d[1]), "+f"(d[2]), "+f"(d[3])
        : "r"(a[0]), "r"(a[1]), "r"(a[2]), "r"(a[3]), "r"(b0), "r"(b1));
}
__device__ __forceinline__ uint32_t h2u(__half2 h) {
    uint32_t u; memcpy(&u, &h, 4); return u;
}

// ===========================================================================
// Kernel 0: elementwise x fp32 -> fp16 (4 float4 per thread for MLP)
// ===========================================================================
__global__ void convx16_kernel(const float* __restrict__ x) {
    size_t base = (size_t)blockIdx.x * 1024 + threadIdx.x;
#pragma unroll
    for (int r = 0; r < 4; r++) {
        size_t i = base + r * 256;
        float4 v = ((const float4*)x)[i];
        uint2 o;
        o.x = h2u(__floats2half2_rn(v.x, v.y));
        o.y = h2u(__floats2half2_rn(v.z, v.w));
        ((uint2*)g_x16)[i] = o;
    }
}

// ===========================================================================
// Kernel 1: QKV projection (R13, banked)
// ===========================================================================
#define PJ_WS 0
#define PJ_X0 33792
#define PJ_X1 67584
#define PJ_SMEM 101376

__global__ __launch_bounds__(256) void proj_kernel(const float* __restrict__ Wq, const float* __restrict__ bq,
                                                   const float* __restrict__ Wk, const float* __restrict__ bk,
                                                   const float* __restrict__ Wv, const float* __restrict__ bv) {
    extern __shared__ __align__(128) char psm[];
    const uint32_t sb = smem_to_u32(psm);
    const int tid = threadIdx.x;
    const int w = tid >> 5, lane = tid & 31;
    const int lq = lane >> 2, lt4 = lane & 3;
    const int wm = w & 3, wn = w >> 2;
    const int b = blockIdx.z;
    const int rowbase = blockIdx.y * 64;
    const int nbase = blockIdx.x * 256;
    const __half* xg = g_x16 + (size_t)b * CC * NN;

#pragma unroll
    for (int i = 0; i < 8; i++) {
        int idx = tid + i * 256, c = idx >> 5, j = idx & 31;
        cp16(sb + PJ_X0 + c * 528 + j * 16, xg + (size_t)c * NN + nbase + j * 8);
    }
    CP_COMMIT();
#pragma unroll
    for (int i = 0; i < 8; i++) {
        int idx = tid + i * 256, c = idx >> 5, j = idx & 31;
        cp16(sb + PJ_X1 + c * 528 + j * 16, xg + (size_t)(64 + c) * NN + nbase + j * 8);
    }
    CP_COMMIT();

#pragma unroll
    for (int i = 0; i < 16; i++) {
        int idx = tid + i * 256;
        int r = idx >> 6, kq = idx & 63;
        int gm = rowbase + r;
        const float* src;
        if (gm < CI)            src = Wq + (size_t)gm * CC;
        else if (gm < 2 * CI)   src = Wk + (size_t)(gm - CI) * CC;
        else                    src = Wv + (size_t)(gm - 2 * CI) * CC;
        float4 v = *(const float4*)(src + kq * 4);
        *(__half2*)(psm + PJ_WS + r * 528 + kq * 8)     = __floats2half2_rn(v.x, v.y);
        *(__half2*)(psm + PJ_WS + r * 528 + kq * 8 + 4) = __floats2half2_rn(v.z, v.w);
    }

    float acc[16][4];
#pragma unroll
    for (int i = 0; i < 16; i++)
#pragma unroll
        for (int e = 0; e < 4; e++) acc[i][e] = 0.f;

    const uint32_t aoffL = (uint32_t)((wm * 16 + (lane & 15)) * 528 + (lane >> 4) * 16);
    const uint32_t xtr = (uint32_t)((lane >> 4) * 8 + (lane & 7));
    const uint32_t ytr = (uint32_t)(((lane >> 3) & 1) * 16);

    CP_WAIT(1);
    __syncthreads();

#pragma unroll
    for (int kc = 0; kc < 4; kc++) {
        const uint32_t xbuf = sb + ((kc & 1) ? PJ_X1 : PJ_X0);
#pragma unroll
        for (int ks = 0; ks < 4; ks++) {
            uint32_t a[4];
            ldsm_x4(a, sb + PJ_WS + aoffL + (kc * 64 + ks * 16) * 2);
#pragma unroll
            for (int nt2 = 0; nt2 < 8; nt2++) {
                uint32_t bf[4];
                ldsm_x4t(bf, xbuf + (ks * 16 + xtr) * 528 + (wn * 128 + nt2 * 16) * 2 + ytr);
                mma16(acc[2 * nt2], a, bf[0], bf[2]);
                mma16(acc[2 * nt2 + 1], a, bf[1], bf[3]);
            }
        }
        __syncthreads();
        if (kc + 2 < 4) {
            uint32_t xdst = sb + ((kc & 1) ? PJ_X1 : PJ_X0);
#pragma unroll
            for (int i = 0; i < 8; i++) {
                int idx = tid + i * 256, c = idx >> 5, j = idx & 31;
                cp16(xdst + c * 528 + j * 16, xg + (size_t)((kc + 2) * 64 + c) * NN + nbase + j * 8);
            }
            CP_COMMIT();
            CP_WAIT(1);
        } else {
            CP_WAIT(0);
        }
        __syncthreads();
    }

    const int m0 = rowbase + wm * 16 + lq, m1 = m0 + 8;
    float bias0, bias1;
    bias0 = (m0 < CI) ? bq[m0] : (m0 < 2 * CI) ? bk[m0 - CI] : bv[m0 - 2 * CI];
    bias1 = (m1 < CI) ? bq[m1] : (m1 < 2 * CI) ? bk[m1 - CI] : bv[m1 - 2 * CI];
    __half* og = g_QKV16 + (size_t)b * ROWS * NN;
#pragma unroll
    for (int nt = 0; nt < 16; nt++) {
        int n = nbase + wn * 128 + nt * 8 + 2 * lt4;
        *(__half2*)(og + (size_t)m0 * NN + n) = __floats2half2_rn(acc[nt][0] + bias0, acc[nt][1] + bias0);
        *(__half2*)(og + (size_t)m1 * NN + n) = __floats2half2_rn(acc[nt][2] + bias1, acc[nt][3] + bias1);
    }
}

// ===========================================================================
// Kernel 2: warp-specialized fp16 flash attention — EXACT best (R5/R13) config.
// ===========================================================================
#define BQ 128
#define BK 64
#define NT (NN / BK)
#define QST 272
#define KVT 144

#define SM_Q    0
#define SM_K0   8704
#define SM_K1   13312
#define SM_V0   17920
#define SM_V1   54784
#define SM_P0   91648
#define SM_P1   110080
#define SM_MREF 128512
#define SM_ALPH 129024
#define SM_LROW 130048
#define SM_FLAG 130560
#define SMEM_AT 130592

#define BID_PRDY 1
#define BID_PFRE 3
#define BID_SBAR 5
#define BID_VBAR 6

__global__ __launch_bounds__(384, 1) void attn_kernel(const float* __restrict__ x,
                                                      const float* __restrict__ gamma_p,
                                                      float* __restrict__ out) {
    extern __shared__ __align__(128) char smem[];
    const uint32_t sb = smem_to_u32(smem);
    float* mref = (float*)(smem + SM_MREF);
    float* alph = (float*)(smem + SM_ALPH);
    float* lrow = (float*)(smem + SM_LROW);
    int* flagv  = (int*)(smem + SM_FLAG);

    const int tid = threadIdx.x;
    const int w = tid >> 5, lane = tid & 31;
    const int lq = lane >> 2, lt4 = lane & 3;
    const int b = blockIdx.y;
    const int qbase = blockIdx.x * BQ;

    const __half* Qg = g_QKV16 + (size_t)b * ROWS * NN;
    const __half* Kg = Qg + (size_t)CI * NN;
    const __half* Vg = Qg + (size_t)2 * CI * NN;

    for (int idx = tid; idx < 512; idx += 384) {
        int c = idx >> 4, j = idx & 15;
        cp16(sb + SM_Q + c * QST + j * 16, Qg + (size_t)c * NN + qbase + j * 8);
    }
    if (tid < 128) {
#pragma unroll
        for (int i = 0; i < 2; i++) {
            int idx = tid + i * 128, c = idx >> 3, j = idx & 7;
            cp16(sb + SM_K0 + c * KVT + j * 16, Kg + (size_t)c * NN + j * 8);
        }
    } else {
        int vt = tid - 128;
#pragma unroll
        for (int i = 0; i < 8; i++) {
            int idx = vt + i * 256, ch = idx >> 3, j = idx & 7;
            cp16(sb + SM_V0 + ch * KVT + j * 16, Vg + (size_t)ch * NN + j * 8);
        }
    }
    CP_COMMIT();
    if (tid < BQ) mref[tid] = -1e30f;
    CP_WAIT(0);
    __syncthreads();

    const uint32_t xtr = (uint32_t)((lane >> 4) * 8 + (lane & 7));
    const uint32_t ytr = (uint32_t)(((lane >> 3) & 1) * 16);
    const uint32_t ant = (uint32_t)((lane & 15) * KVT + (lane >> 4) * 16);
    const uint32_t bnt = (uint32_t)((((lane >> 3) & 1) * 8 + (lane & 7)) * KVT + (lane >> 4) * 16);

    if (w < 4) {
        // =================== S-warps ===================
        const int sw = w;
        uint32_t aq[2][2][4];
#pragma unroll
        for (int rg = 0; rg < 2; rg++)
#pragma unroll
            for (int ks = 0; ks < 2; ks++)
                ldsm_x4t(aq[rg][ks], sb + SM_Q + (ks * 16 + xtr) * QST + (sw * 32 + rg * 16) * 2 + ytr);

        float l00 = 0.f, l01 = 0.f, l10 = 0.f, l11 = 0.f;

#pragma unroll 1
        for (int t = 0; t < NT; t++) {
            const int bi = t & 1;
            BAR_SYNC(BID_SBAR, 128);
            if (t + 1 < NT) {
                uint32_t kd = sb + ((t + 1) & 1 ? SM_K1 : SM_K0);
                const int kt1 = (t + 1) * BK;
#pragma unroll
                for (int i = 0; i < 2; i++) {
                    int idx = tid + i * 128, c = idx >> 3, j = idx & 7;
                    cp16(kd + c * KVT + j * 16, Kg + (size_t)c * NN + kt1 + j * 8);
                }
                CP_COMMIT();
                CP_WAIT(1);
            } else {
                CP_WAIT(0);
            }
            BAR_SYNC(BID_SBAR, 128);

            const uint32_t kbuf = sb + (bi ? SM_K1 : SM_K0);
            float sacc[2][8][4];
#pragma unroll
            for (int rg = 0; rg < 2; rg++)
#pragma unroll
                for (int nt = 0; nt < 8; nt++)
#pragma unroll
                    for (int e = 0; e < 4; e++) sacc[rg][nt][e] = 0.f;
#pragma unroll
            for (int ks = 0; ks < 2; ks++) {
#pragma unroll
                for (int nt2 = 0; nt2 < 4; nt2++) {
                    uint32_t kb[4];
                    ldsm_x4t(kb, kbuf + (ks * 16 + xtr) * KVT + nt2 * 32 + ytr);
#pragma unroll
                    for (int rg = 0; rg < 2; rg++) {
                        mma16(sacc[rg][2 * nt2], aq[rg][ks], kb[0], kb[2]);
                        mma16(sacc[rg][2 * nt2 + 1], aq[rg][ks], kb[1], kb[3]);
                    }
                }
            }

            BAR_SYNC(BID_PFRE + bi, 384);

            bool anyflag = false;
#pragma unroll
            for (int rg = 0; rg < 2; rg++) {
                const int row0 = sw * 32 + rg * 16 + lq, row1 = row0 + 8;
                float tm0 = -1e30f, tm1 = -1e30f;
#pragma unroll
                for (int nt = 0; nt < 8; nt++) {
                    tm0 = fmaxf(tm0, fmaxf(sacc[rg][nt][0], sacc[rg][nt][1]));
                    tm1 = fmaxf(tm1, fmaxf(sacc[rg][nt][2], sacc[rg][nt][3]));
                }
                tm0 = fmaxf(tm0, __shfl_xor_sync(0xffffffffu, tm0, 1));
                tm0 = fmaxf(tm0, __shfl_xor_sync(0xffffffffu, tm0, 2));
                tm1 = fmaxf(tm1, __shfl_xor_sync(0xffffffffu, tm1, 1));
                tm1 = fmaxf(tm1, __shfl_xor_sync(0xffffffffu, tm1, 2));
                const float mold0 = mref[row0], mold1 = mref[row1];
                const float mnew0 = (tm0 > mold0 + 6.f) ? tm0 : mold0;
                const float mnew1 = (tm1 > mold1 + 6.f) ? tm1 : mold1;
                const float alpha0 = __expf(mold0 - mnew0);
                const float alpha1 = __expf(mold1 - mnew1);
                if (lt4 == 0) {
                    mref[row0] = mnew0; alph[bi * 128 + row0] = alpha0;
                    mref[row1] = mnew1; alph[bi * 128 + row1] = alpha1;
                }
                anyflag |= (mnew0 != mold0) | (mnew1 != mold1);
                float ts0 = 0.f, ts1 = 0.f;
#pragma unroll
                for (int nt = 0; nt < 8; nt++) {
                    float p0 = __expf(sacc[rg][nt][0] - mnew0);
                    float p1 = __expf(sacc[rg][nt][1] - mnew0);
                    float p2 = __expf(sacc[rg][nt][2] - mnew1);
                    float p3 = __expf(sacc[rg][nt][3] - mnew1);
                    ts0 += p0 + p1; ts1 += p2 + p3;
                    int mb = (nt * 8 + 2 * lt4) * 2;
                    *(__half2*)(smem + (bi ? SM_P1 : SM_P0) + row0 * KVT + mb) = __floats2half2_rn(p0, p1);
                    *(__half2*)(smem + (bi ? SM_P1 : SM_P0) + row1 * KVT + mb) = __floats2half2_rn(p2, p3);
                }
                if (rg == 0) { l00 = l00 * alpha0 + ts0; l01 = l01 * alpha1 + ts1; }
                else         { l10 = l10 * alpha0 + ts0; l11 = l11 * alpha1 + ts1; }
            }
            int any = __any_sync(0xffffffffu, anyflag);
            if (lane == 0) flagv[bi * 4 + sw] = any;
            BAR_ARRIVE(BID_PRDY + bi, 384);
        }

        l00 += __shfl_xor_sync(0xffffffffu, l00, 1); l00 += __shfl_xor_sync(0xffffffffu, l00, 2);
        l01 += __shfl_xor_sync(0xffffffffu, l01, 1); l01 += __shfl_xor_sync(0xffffffffu, l01, 2);
        l10 += __shfl_xor_sync(0xffffffffu, l10, 1); l10 += __shfl_xor_sync(0xffffffffu, l10, 2);
        l11 += __shfl_xor_sync(0xffffffffu, l11, 1); l11 += __shfl_xor_sync(0xffffffffu, l11, 2);
        if (lt4 == 0) {
            lrow[sw * 32 + lq] = l00;       lrow[sw * 32 + lq + 8] = l01;
            lrow[sw * 32 + 16 + lq] = l10;  lrow[sw * 32 + 16 + lq + 8] = l11;
        }
        __syncthreads();
    } else {
        // =================== V-warps ===================
        const int vw = w - 4;
        BAR_ARRIVE(BID_PFRE + 0, 384);
        BAR_ARRIVE(BID_PFRE + 1, 384);

        float Oacc[128];
#pragma unroll
        for (int i = 0; i < 128; i++) Oacc[i] = 0.f;

#pragma unroll 1
        for (int t = 0; t < NT; t++) {
            const int bi = t & 1;
            BAR_SYNC(BID_VBAR, 256);
            if (t + 1 < NT) {
                uint32_t vd = sb + ((t + 1) & 1 ? SM_V1 : SM_V0);
                const int kt1 = (t + 1) * BK;
                int vt = tid - 128;
#pragma unroll
                for (int i = 0; i < 8; i++) {
                    int idx = vt + i * 256, ch = idx >> 3, j = idx & 7;
                    cp16(vd + ch * KVT + j * 16, Vg + (size_t)ch * NN + kt1 + j * 8);
                }
                CP_COMMIT();
                CP_WAIT(1);
            } else {
                CP_WAIT(0);
            }
            BAR_SYNC(BID_VBAR, 256);
            BAR_SYNC(BID_PRDY + bi, 384);

            int flag = flagv[bi * 4] | flagv[bi * 4 + 1] | flagv[bi * 4 + 2] | flagv[bi * 4 + 3];
            if (flag) {
#pragma unroll
                for (int mt = 0; mt < 8; mt++) {
                    float a0 = alph[bi * 128 + mt * 16 + lq];
                    float a1 = alph[bi * 128 + mt * 16 + lq + 8];
#pragma unroll
                    for (int nt = 0; nt < 4; nt++) {
                        float* o = &Oacc[(mt * 4 + nt) * 4];
                        o[0] *= a0; o[1] *= a0; o[2] *= a1; o[3] *= a1;
                    }
                }
            }
            const uint32_t vbuf = sb + (bi ? SM_V1 : SM_V0);
            const uint32_t pbuf = sb + (bi ? SM_P1 : SM_P0);
#pragma unroll
            for (int ks = 0; ks < 4; ks++) {
                uint32_t vb0[4], vb1[4];
                {
                    uint32_t tr[4];
                    ldsm_x4(tr, vbuf + bnt + (vw * 32) * KVT + ks * 32);
                    vb0[0] = tr[0]; vb0[1] = tr[1]; vb1[0] = tr[2]; vb1[1] = tr[3];
                    ldsm_x4(tr, vbuf + bnt + (vw * 32 + 16) * KVT + ks * 32);
                    vb0[2] = tr[0]; vb0[3] = tr[1]; vb1[2] = tr[2]; vb1[3] = tr[3];
                }
#pragma unroll
                for (int mt = 0; mt < 8; mt++) {
                    uint32_t a[4];
                    ldsm_x4(a, pbuf + ant + (mt * 16) * KVT + ks * 32);
#pragma unroll
                    for (int nt = 0; nt < 4; nt++)
                        mma16(&Oacc[(mt * 4 + nt) * 4], a, vb0[nt], vb1[nt]);
                }
            }
            BAR_ARRIVE(BID_PFRE + bi, 384);
        }

        __syncthreads();

        const float g = gamma_p[0];
        const float* xb = x + (size_t)b * CC * NN;
        float* ob = out + (size_t)b * CC * NN;
#pragma unroll
        for (int mt = 0; mt < 8; mt++) {
            float s0 = g / lrow[mt * 16 + lq];
            float s1 = g / lrow[mt * 16 + lq + 8];
            int na = qbase + mt * 16 + lq;
#pragma unroll
            for (int nt = 0; nt < 4; nt++) {
                int ch = vw * 32 + nt * 8 + 2 * lt4;
                const float* o = &Oacc[(mt * 4 + nt) * 4];
                size_t i00 = (size_t)ch * NN + na;
                size_t i10 = (size_t)(ch + 1) * NN + na;
                ob[i00] = o[0] * s0 + xb[i00];
                ob[i10] = o[1] * s0 + xb[i10];
                ob[i00 + 8] = o[2] * s1 + xb[i00 + 8];
                ob[i10 + 8] = o[3] * s1 + xb[i10 + 8];
            }
        }
    }
}

// ===========================================================================
// Launch
// ===========================================================================
extern "C" void kernel_launch(void* const* d_in, const int* in_sizes, int n_in,
                              void* d_out, int out_size) {
    const float* x  = (const float*)d_in[0];
    const float* Wq = (const float*)d_in[1];
    const float* bq = (const float*)d_in[2];
    const float* Wk = (const float*)d_in[3];
    const float* bk = (const float*)d_in[4];
    const float* Wv = (const float*)d_in[5];
    const float* bv = (const float*)d_in[6];
    const float* gamma = (const float*)d_in[7];
    float* out = (float*)d_out;

    static int cfg = 0;
    if (!cfg) {
        cudaFuncSetAttribute(proj_kernel, cudaFuncAttributeMaxDynamicSharedMemorySize, PJ_SMEM);
        cudaFuncSetAttribute(attn_kernel, cudaFuncAttributeMaxDynamicSharedMemorySize, SMEM_AT);
        cfg = 1;
    }

    convx16_kernel<<<(BB * CC * NN / 4) / 1024, 256>>>(x);

    dim3 pgrid(NN / 256, ROWS / 64, BB);
    proj_kernel<<<pgrid, 256, PJ_SMEM>>>(Wq, bq, Wk, bk, Wv, bv);

    dim3 agrid(NN / BQ, BB);
    attn_kernel<<<agrid, 384, SMEM_AT>>>(x, gamma, out);
}